// round 2
// baseline (speedup 1.0000x reference)
#include <cuda_runtime.h>
#include <cuda_bf16.h>

#define N_NODES 50000
#define N_NEXT  2000
#define D       128
#define E_MAX   1600000
#define BM 128
#define BN 128
#define BK 16

// ---------------- scratch (device globals; no allocation allowed) ----------------
__device__ float g_H[(size_t)N_NODES * D];      // pre-aggregation features (norm_out applied)
__device__ float g_Pp[N_NEXT * D];              // (next_h @ W_fus) * topDown_w
__device__ float g_Wcp[D * D];                  // W_conv * conv_w
__device__ float g_bias[D];                     // b_conv*conv_w + b_fus*topDown_w
__device__ int   g_in_cnt[N_NODES];
__device__ int   g_out_cnt[N_NODES];
__device__ int   g_row_ofs[N_NODES + 1];
__device__ int   g_cursor[N_NODES];
__device__ int   g_csr_src[E_MAX];

// ---------------- f32x2 packed-math helpers ----------------
__device__ __forceinline__ unsigned long long pack2(float x, float y) {
    unsigned long long r;
    asm("mov.b64 %0, {%1, %2};" : "=l"(r) : "f"(x), "f"(y));
    return r;
}
__device__ __forceinline__ void fma2(unsigned long long& d, unsigned long long a, unsigned long long b) {
    asm("fma.rn.f32x2 %0, %1, %2, %3;" : "=l"(d) : "l"(a), "l"(b), "l"(d));
}
__device__ __forceinline__ float2 unpack2(unsigned long long v) {
    float x, y;
    asm("mov.b64 {%0, %1}, %2;" : "=f"(x), "=f"(y) : "l"(v));
    return make_float2(x, y);
}

__device__ __forceinline__ int clampi(int v, int lo, int hi) {
    return v < lo ? lo : (v > hi ? hi : v);
}

// ---------------- small kernels ----------------
__global__ void k_init() {
    int i = blockIdx.x * blockDim.x + threadIdx.x;
    if (i < N_NODES) { g_in_cnt[i] = 0; g_out_cnt[i] = 0; g_cursor[i] = 0; }
}

__global__ void k_count(const int* __restrict__ src, const int* __restrict__ dst, int E) {
    int e = blockIdx.x * blockDim.x + threadIdx.x;
    if (e < E) {
        atomicAdd(&g_out_cnt[clampi(src[e], 0, N_NODES - 1)], 1);
        atomicAdd(&g_in_cnt[clampi(dst[e], 0, N_NODES - 1)], 1);
    }
}

// single-block exclusive scan of g_in_cnt -> g_row_ofs
__global__ void k_scan(int n) {
    __shared__ int sh[1024];
    __shared__ int s_carry;
    int t = threadIdx.x;
    if (t == 0) s_carry = 0;
    __syncthreads();
    for (int base = 0; base < n; base += 1024) {
        int i = base + t;
        int v = (i < n) ? g_in_cnt[i] : 0;
        sh[t] = v;
        __syncthreads();
        for (int off = 1; off < 1024; off <<= 1) {
            int tv = (t >= off) ? sh[t - off] : 0;
            __syncthreads();
            sh[t] += tv;
            __syncthreads();
        }
        if (i < n) g_row_ofs[i] = s_carry + sh[t] - v;
        __syncthreads();
        if (t == 1023) s_carry += sh[1023];
        __syncthreads();
    }
    if (t == 0) g_row_ofs[n] = s_carry;
}

__global__ void k_fill(const int* __restrict__ src, const int* __restrict__ dst, int E) {
    int e = blockIdx.x * blockDim.x + threadIdx.x;
    if (e < E) {
        int d = clampi(dst[e], 0, N_NODES - 1);
        int pos = g_row_ofs[d] + atomicAdd(&g_cursor[d], 1);
        g_csr_src[pos] = clampi(src[e], 0, N_NODES - 1);
    }
}

__global__ void k_prepW(const float* __restrict__ W_conv, const float* __restrict__ conv_w,
                        const float* __restrict__ b_conv, const float* __restrict__ b_fus,
                        const float* __restrict__ tdw) {
    int i = blockIdx.x * blockDim.x + threadIdx.x;
    if (i < D * D) g_Wcp[i] = W_conv[i] * conv_w[i & (D - 1)];
    if (i < D)     g_bias[i] = b_conv[i] * conv_w[i] + b_fus[i] * tdw[i];
}

// Pp = (next_h @ W_fus) * tdw ; 16 rows per block
__global__ void k_prepP(const float* __restrict__ next_h, const float* __restrict__ W_fus,
                        const float* __restrict__ tdw) {
    __shared__ float sh[16][D];
    int r0 = blockIdx.x * 16;
    int j = threadIdx.x;
    #pragma unroll
    for (int r = 0; r < 16; r++) sh[r][j] = next_h[(r0 + r) * D + j];
    __syncthreads();
    float acc[16];
    #pragma unroll
    for (int r = 0; r < 16; r++) acc[r] = 0.f;
    for (int k = 0; k < D; k++) {
        float w = W_fus[k * D + j];
        #pragma unroll
        for (int r = 0; r < 16; r++) acc[r] += sh[r][k] * w;
    }
    float t = tdw[j];
    #pragma unroll
    for (int r = 0; r < 16; r++) g_Pp[(r0 + r) * D + j] = acc[r] * t;
}

// ---------------- fused GEMM: H = norm_out .* (curr_h@Wcp + inc@Pp) ----------------
__global__ __launch_bounds__(256, 2) void k_gemm(const float* __restrict__ curr_h,
                                                 const float* __restrict__ inc) {
    __shared__ float As[2][BK][BM + 4];
    __shared__ float Bs[2][BK][BN];
    const int tid = threadIdx.x;
    const int bm = blockIdx.x * BM;
    const int tx = tid & 15;
    const int ty = tid >> 4;
    const int a_r = tid >> 2;          // 0..63
    const int a_c = (tid & 3) * 4;     // 0,4,8,12
    const int b_r = tid >> 5;          // 0..7
    const int b_c = (tid & 31) * 4;

    unsigned long long acc[8][4];
    #pragma unroll
    for (int r = 0; r < 8; r++)
        #pragma unroll
        for (int c = 0; c < 4; c++) acc[r][c] = 0ull;

    float4 a_reg[2], b_reg[2];

    auto g_loadA = [&](const float* Am, int ld, int k0) {
        #pragma unroll
        for (int p = 0; p < 2; p++) {
            int row = bm + a_r + p * 64;
            row = row < N_NODES ? row : N_NODES - 1;
            a_reg[p] = *reinterpret_cast<const float4*>(Am + (size_t)row * ld + k0 + a_c);
        }
    };
    auto g_loadB = [&](const float* Bm, int k0) {
        #pragma unroll
        for (int p = 0; p < 2; p++)
            b_reg[p] = *reinterpret_cast<const float4*>(Bm + (k0 + b_r + p * 8) * D + b_c);
    };
    auto s_store = [&](int buf) {
        #pragma unroll
        for (int p = 0; p < 2; p++) {
            As[buf][a_c + 0][a_r + p * 64] = a_reg[p].x;
            As[buf][a_c + 1][a_r + p * 64] = a_reg[p].y;
            As[buf][a_c + 2][a_r + p * 64] = a_reg[p].z;
            As[buf][a_c + 3][a_r + p * 64] = a_reg[p].w;
            *reinterpret_cast<float4*>(&Bs[buf][b_r + p * 8][b_c]) = b_reg[p];
        }
    };
    auto compute = [&](int buf) {
        #pragma unroll
        for (int kk = 0; kk < BK; kk++) {
            float4 a0 = *reinterpret_cast<const float4*>(&As[buf][kk][ty * 8]);
            float4 a1 = *reinterpret_cast<const float4*>(&As[buf][kk][ty * 8 + 4]);
            const unsigned long long* bp =
                reinterpret_cast<const unsigned long long*>(&Bs[buf][kk][tx * 8]);
            unsigned long long b0 = bp[0], b1 = bp[1], b2 = bp[2], b3 = bp[3];
            float av[8] = {a0.x, a0.y, a0.z, a0.w, a1.x, a1.y, a1.z, a1.w};
            #pragma unroll
            for (int r = 0; r < 8; r++) {
                unsigned long long aa = pack2(av[r], av[r]);
                fma2(acc[r][0], aa, b0);
                fma2(acc[r][1], aa, b1);
                fma2(acc[r][2], aa, b2);
                fma2(acc[r][3], aa, b3);
            }
        }
    };
    auto run_phase = [&](const float* Am, int ld, int K, const float* Bm) {
        __syncthreads();
        g_loadA(Am, ld, 0);
        g_loadB(Bm, 0);
        s_store(0);
        __syncthreads();
        int buf = 0;
        const int nt = K / BK;
        for (int kt = 0; kt < nt; kt++) {
            if (kt + 1 < nt) { g_loadA(Am, ld, (kt + 1) * BK); g_loadB(Bm, (kt + 1) * BK); }
            compute(buf);
            if (kt + 1 < nt) s_store(buf ^ 1);
            __syncthreads();
            buf ^= 1;
        }
    };

    run_phase(curr_h, D, D, g_Wcp);
    run_phase(inc, N_NEXT, N_NEXT, g_Pp);

    // epilogue: apply norm_out, write H
    #pragma unroll
    for (int r = 0; r < 8; r++) {
        int grow = bm + ty * 8 + r;
        if (grow >= N_NODES) continue;
        float no = rsqrtf((float)(g_out_cnt[grow] + 1));
        float v[8];
        #pragma unroll
        for (int c = 0; c < 4; c++) {
            float2 p = unpack2(acc[r][c]);
            v[2 * c] = p.x * no;
            v[2 * c + 1] = p.y * no;
        }
        float4* d4 = reinterpret_cast<float4*>(g_H + (size_t)grow * D + tx * 8);
        d4[0] = make_float4(v[0], v[1], v[2], v[3]);
        d4[1] = make_float4(v[4], v[5], v[6], v[7]);
    }
}

// ---------------- gather (SpMM) + norm_in + bias + LayerNorm + ReLU ----------------
__global__ void k_gather(const float* __restrict__ ln_g, const float* __restrict__ ln_b,
                         float* __restrict__ out) {
    int warp = (blockIdx.x * blockDim.x + threadIdx.x) >> 5;
    int lane = threadIdx.x & 31;
    if (warp >= N_NODES) return;

    // self-loop contribution = own row
    float4 acc = reinterpret_cast<const float4*>(g_H + (size_t)warp * D)[lane];
    int beg = g_row_ofs[warp];
    int end = g_row_ofs[warp + 1];

    for (int base = beg; base < end; base += 32) {
        int idx = base + lane;
        int s = (idx < end) ? g_csr_src[idx] : 0;
        int cnt = min(32, end - base);
        for (int j = 0; j < cnt; j++) {
            int ss = __shfl_sync(0xffffffffu, s, j);
            float4 v = reinterpret_cast<const float4*>(g_H + (size_t)ss * D)[lane];
            acc.x += v.x; acc.y += v.y; acc.z += v.z; acc.w += v.w;
        }
    }

    float ni = rsqrtf((float)(end - beg + 1));
    int c0 = lane * 4;
    float x0 = acc.x * ni + g_bias[c0 + 0];
    float x1 = acc.y * ni + g_bias[c0 + 1];
    float x2 = acc.z * ni + g_bias[c0 + 2];
    float x3 = acc.w * ni + g_bias[c0 + 3];

    float s = x0 + x1 + x2 + x3;
    #pragma unroll
    for (int off = 16; off > 0; off >>= 1) s += __shfl_xor_sync(0xffffffffu, s, off);
    float mu = s * (1.0f / D);
    float d0 = x0 - mu, d1 = x1 - mu, d2 = x2 - mu, d3 = x3 - mu;
    float q = d0 * d0 + d1 * d1 + d2 * d2 + d3 * d3;
    #pragma unroll
    for (int off = 16; off > 0; off >>= 1) q += __shfl_xor_sync(0xffffffffu, q, off);
    float inv = rsqrtf(q * (1.0f / D) + 1e-5f);

    float4 o;
    o.x = fmaxf(d0 * inv * ln_g[c0 + 0] + ln_b[c0 + 0], 0.f);
    o.y = fmaxf(d1 * inv * ln_g[c0 + 1] + ln_b[c0 + 1], 0.f);
    o.z = fmaxf(d2 * inv * ln_g[c0 + 2] + ln_b[c0 + 2], 0.f);
    o.w = fmaxf(d3 * inv * ln_g[c0 + 3] + ln_b[c0 + 3], 0.f);
    reinterpret_cast<float4*>(out + (size_t)warp * D)[lane] = o;
}

// ---------------- launcher ----------------
extern "C" void kernel_launch(void* const* d_in, const int* in_sizes, int n_in,
                              void* d_out, int out_size) {
    const float* curr_h = (const float*)d_in[0];
    const float* next_h = (const float*)d_in[1];
    const float* inc    = (const float*)d_in[2];
    const int*   src    = (const int*)d_in[3];
    const int*   dst    = (const int*)d_in[4];
    const float* W_conv = (const float*)d_in[5];
    const float* b_conv = (const float*)d_in[6];
    const float* W_fus  = (const float*)d_in[7];
    const float* b_fus  = (const float*)d_in[8];
    const float* conv_w = (const float*)d_in[9];
    const float* tdw    = (const float*)d_in[10];
    const float* ln_g   = (const float*)d_in[11];
    const float* ln_b   = (const float*)d_in[12];
    float* out = (float*)d_out;
    const int E = in_sizes[3];

    k_init<<<(N_NODES + 255) / 256, 256>>>();
    k_count<<<(E + 255) / 256, 256>>>(src, dst, E);
    k_scan<<<1, 1024>>>(N_NODES);
    k_fill<<<(E + 255) / 256, 256>>>(src, dst, E);
    k_prepW<<<(D * D + 255) / 256, 256>>>(W_conv, conv_w, b_conv, b_fus, tdw);
    k_prepP<<<N_NEXT / 16, 128>>>(next_h, W_fus, tdw);
    k_gemm<<<(N_NODES + BM - 1) / BM, 256>>>(curr_h, inc);
    k_gather<<<(N_NODES * 32 + 255) / 256, 256>>>(ln_g, ln_b, out);
}

// round 4
// speedup vs baseline: 1.2709x; 1.2709x over previous
#include <cuda_runtime.h>
#include <cstdint>

#define N_NODES 50000
#define N_NEXT  2000
#define D       128
#define E_MAX   1600000

#define KB        32
#define NCH_A     63                   // ceil(2000/32)
#define NCH_TOT   67                   // + 128/32 for curr_h phase
#define CHUNK_FLOATS 4096              // 4 ksteps * 16 atoms * 32 lanes * 2

// ---------------- scratch ----------------
__device__ float g_H[(size_t)N_NODES * D];
__device__ float g_Pp[(size_t)N_NEXT * D];                 // (next_h@W_fus)*tdw, fp32
__device__ float g_BF[(size_t)NCH_TOT * CHUNK_FLOATS];     // B in mma-fragment order, tf32-rounded
__device__ float g_bias[D];
__device__ int   g_in_cnt[N_NODES];
__device__ int   g_out_cnt[N_NODES];
__device__ int   g_row_ofs[N_NODES + 1];
__device__ int   g_cursor[N_NODES];
__device__ int   g_csr_src[E_MAX];

// ---------------- helpers ----------------
__device__ __forceinline__ uint32_t tf32r(float x) {
    uint32_t u;
    asm("cvt.rna.tf32.f32 %0, %1;" : "=r"(u) : "f"(x));
    return u;
}
__device__ __forceinline__ uint32_t smem_u32(const void* p) {
    uint32_t a;
    asm("{ .reg .u64 t; cvta.to.shared.u64 t, %1; cvt.u32.u64 %0, t; }" : "=r"(a) : "l"(p));
    return a;
}
__device__ __forceinline__ void cp16(uint32_t s, const void* g) {
    asm volatile("cp.async.cg.shared.global [%0], [%1], 16;" :: "r"(s), "l"(g) : "memory");
}
__device__ __forceinline__ void mma8(float* c, uint32_t a0, uint32_t a1, uint32_t a2, uint32_t a3,
                                     uint32_t b0, uint32_t b1) {
    asm volatile(
        "mma.sync.aligned.m16n8k8.row.col.f32.tf32.tf32.f32 "
        "{%0,%1,%2,%3}, {%4,%5,%6,%7}, {%8,%9}, {%0,%1,%2,%3};"
        : "+f"(c[0]), "+f"(c[1]), "+f"(c[2]), "+f"(c[3])
        : "r"(a0), "r"(a1), "r"(a2), "r"(a3), "r"(b0), "r"(b1));
}
__device__ __forceinline__ int clampi(int v, int lo, int hi) {
    return v < lo ? lo : (v > hi ? hi : v);
}

// ---------------- CSR build ----------------
__global__ void k_init() {
    int i = blockIdx.x * blockDim.x + threadIdx.x;
    if (i < N_NODES) { g_in_cnt[i] = 0; g_out_cnt[i] = 0; g_cursor[i] = 0; }
}

__global__ void k_count(const int* __restrict__ src, const int* __restrict__ dst, int E) {
    int e = blockIdx.x * blockDim.x + threadIdx.x;
    if (e < E) {
        atomicAdd(&g_out_cnt[clampi(src[e], 0, N_NODES - 1)], 1);
        atomicAdd(&g_in_cnt[clampi(dst[e], 0, N_NODES - 1)], 1);
    }
}

__global__ void k_scan(int n) {
    __shared__ int sh[1024];
    __shared__ int s_carry;
    int t = threadIdx.x;
    if (t == 0) s_carry = 0;
    __syncthreads();
    for (int base = 0; base < n; base += 1024) {
        int i = base + t;
        int v = (i < n) ? g_in_cnt[i] : 0;
        sh[t] = v;
        __syncthreads();
        for (int off = 1; off < 1024; off <<= 1) {
            int tv = (t >= off) ? sh[t - off] : 0;
            __syncthreads();
            sh[t] += tv;
            __syncthreads();
        }
        if (i < n) g_row_ofs[i] = s_carry + sh[t] - v;
        __syncthreads();
        if (t == 1023) s_carry += sh[1023];
        __syncthreads();
    }
    if (t == 0) g_row_ofs[n] = s_carry;
}

__global__ void k_fill(const int* __restrict__ src, const int* __restrict__ dst, int E) {
    int e = blockIdx.x * blockDim.x + threadIdx.x;
    if (e < E) {
        int d = clampi(dst[e], 0, N_NODES - 1);
        int pos = g_row_ofs[d] + atomicAdd(&g_cursor[d], 1);
        g_csr_src[pos] = clampi(src[e], 0, N_NODES - 1);
    }
}

// ---------------- prep ----------------
__global__ void k_prepBias(const float* __restrict__ b_conv, const float* __restrict__ b_fus,
                           const float* __restrict__ conv_w, const float* __restrict__ tdw) {
    int i = threadIdx.x;
    if (i < D) g_bias[i] = b_conv[i] * conv_w[i] + b_fus[i] * tdw[i];
}

// Pp = (next_h @ W_fus) * tdw ; 16 rows per block, fp32
__global__ void k_prepP(const float* __restrict__ next_h, const float* __restrict__ W_fus,
                        const float* __restrict__ tdw) {
    __shared__ float sh[16][D];
    int r0 = blockIdx.x * 16;
    int j = threadIdx.x;
    #pragma unroll
    for (int r = 0; r < 16; r++) sh[r][j] = next_h[(r0 + r) * D + j];
    __syncthreads();
    float acc[16];
    #pragma unroll
    for (int r = 0; r < 16; r++) acc[r] = 0.f;
    for (int k = 0; k < D; k++) {
        float w = W_fus[k * D + j];
        #pragma unroll
        for (int r = 0; r < 16; r++) acc[r] += sh[r][k] * w;
    }
    float t = tdw[j];
    #pragma unroll
    for (int r = 0; r < 16; r++) g_Pp[(size_t)(r0 + r) * D + j] = acc[r] * t;
}

// pack B (Pp for chunks 0..62, W_conv*conv_w for 63..66) into mma-fragment order, tf32-rounded.
// layout per chunk: [ks][j][lane][e] : b_e = B[k = c*32 + ks*8 + tg + 4e][n = j*8 + g]
__global__ void k_packB(const float* __restrict__ W_conv, const float* __restrict__ conv_w) {
    int i = blockIdx.x * blockDim.x + threadIdx.x;
    if (i >= NCH_TOT * CHUNK_FLOATS) return;
    int c = i / CHUNK_FLOATS, rem = i % CHUNK_FLOATS;
    int ks = rem >> 10;
    int rem2 = rem & 1023;
    int j = rem2 >> 6;
    int l2 = rem2 & 63;
    int lane = l2 >> 1, e = l2 & 1;
    int g = lane >> 2, tg = lane & 3;
    int n = j * 8 + g;
    int kk = ks * 8 + tg + e * 4;
    float v;
    if (c < NCH_A) {
        int kg = c * KB + kk;
        v = (kg < N_NEXT) ? g_Pp[(size_t)kg * D + n] : 0.f;
    } else {
        int kg = (c - NCH_A) * KB + kk;
        v = W_conv[kg * D + n] * conv_w[n];
    }
    g_BF[i] = __uint_as_float(tf32r(v));
}

// ---------------- tf32 mma.sync GEMM: H = norm_out .* (inc@Pp + curr_h@Wcp) ----------------
__global__ __launch_bounds__(256, 2) void k_gemm_mma(const float* __restrict__ curr_h,
                                                     const float* __restrict__ inc) {
    __shared__ float sB[2][CHUNK_FLOATS];     // 32 KB
    const int tid = threadIdx.x;
    const int wid = tid >> 5, lane = tid & 31;
    const int g = lane >> 2, tg = lane & 3;
    const int bm = blockIdx.x * 128;
    const int m0 = bm + wid * 16;
    const int r0 = m0 + g, r1 = m0 + g + 8;
    const int r0c = min(r0, N_NODES - 1), r1c = min(r1, N_NODES - 1);
    const float* A0i = inc + (size_t)r0c * N_NEXT;
    const float* A1i = inc + (size_t)r1c * N_NEXT;
    const float* A0h = curr_h + (size_t)r0c * D;
    const float* A1h = curr_h + (size_t)r1c * D;

    float acc[16][4];
    #pragma unroll
    for (int j = 0; j < 16; j++)
        #pragma unroll
        for (int q = 0; q < 4; q++) acc[j][q] = 0.f;

    const uint32_t sb0 = smem_u32(&sB[0][0]);

    auto fetchB = [&](int c, int buf) {
        const float* src = g_BF + (size_t)c * CHUNK_FLOATS + tid * 16;
        uint32_t dst = sb0 + (uint32_t)buf * (CHUNK_FLOATS * 4) + tid * 64;
        cp16(dst, src); cp16(dst + 16, src + 4); cp16(dst + 32, src + 8); cp16(dst + 48, src + 12);
        asm volatile("cp.async.commit_group;" ::: "memory");
    };

    float aBuf[2][16];
    auto loadA = [&](int c, float* ab) {
        #pragma unroll
        for (int ks = 0; ks < 4; ks++) {
            int kk = ks * 8 + tg;
            if (c < NCH_A) {
                int kg0 = c * KB + kk, kg1 = kg0 + 4;
                bool v0 = kg0 < N_NEXT, v1 = kg1 < N_NEXT;
                ab[ks * 4 + 0] = v0 ? __ldg(A0i + kg0) : 0.f;
                ab[ks * 4 + 1] = v0 ? __ldg(A1i + kg0) : 0.f;
                ab[ks * 4 + 2] = v1 ? __ldg(A0i + kg1) : 0.f;
                ab[ks * 4 + 3] = v1 ? __ldg(A1i + kg1) : 0.f;
            } else {
                int kg0 = (c - NCH_A) * KB + kk;
                ab[ks * 4 + 0] = __ldg(A0h + kg0);
                ab[ks * 4 + 1] = __ldg(A1h + kg0);
                ab[ks * 4 + 2] = __ldg(A0h + kg0 + 4);
                ab[ks * 4 + 3] = __ldg(A1h + kg0 + 4);
            }
        }
    };

    fetchB(0, 0);
    loadA(0, aBuf[0]);

    for (int c = 0; c < NCH_TOT; ++c) {
        const int cb = c & 1;
        if (c + 1 < NCH_TOT) {
            fetchB(c + 1, cb ^ 1);
            loadA(c + 1, aBuf[cb ^ 1]);
            asm volatile("cp.async.wait_group 1;" ::: "memory");
        } else {
            asm volatile("cp.async.wait_group 0;" ::: "memory");
        }
        __syncthreads();

        const float* ab = aBuf[cb];
        const float* bbase = &sB[cb][0];
        #pragma unroll
        for (int ks = 0; ks < 4; ks++) {
            uint32_t a0 = tf32r(ab[ks * 4 + 0]);
            uint32_t a1 = tf32r(ab[ks * 4 + 1]);
            uint32_t a2 = tf32r(ab[ks * 4 + 2]);
            uint32_t a3 = tf32r(ab[ks * 4 + 3]);
            #pragma unroll
            for (int j = 0; j < 16; j++) {
                float2 b = *reinterpret_cast<const float2*>(bbase + (ks * 16 + j) * 64 + lane * 2);
                mma8(acc[j], a0, a1, a2, a3,
                     __float_as_uint(b.x), __float_as_uint(b.y));
            }
        }
        __syncthreads();
    }

    // epilogue: apply norm_out, write H
    float no0 = rsqrtf((float)(g_out_cnt[r0c] + 1));
    float no1 = rsqrtf((float)(g_out_cnt[r1c] + 1));
    if (r0 < N_NODES) {
        float* d = g_H + (size_t)r0 * D + tg * 2;
        #pragma unroll
        for (int j = 0; j < 16; j++)
            *reinterpret_cast<float2*>(d + j * 8) = make_float2(acc[j][0] * no0, acc[j][1] * no0);
    }
    if (r1 < N_NODES) {
        float* d = g_H + (size_t)r1 * D + tg * 2;
        #pragma unroll
        for (int j = 0; j < 16; j++)
            *reinterpret_cast<float2*>(d + j * 8) = make_float2(acc[j][2] * no1, acc[j][3] * no1);
    }
}

// ---------------- gather + norm_in + bias + LayerNorm + ReLU ----------------
__global__ void k_gather(const float* __restrict__ ln_g, const float* __restrict__ ln_b,
                         float* __restrict__ out) {
    int warp = (blockIdx.x * blockDim.x + threadIdx.x) >> 5;
    int lane = threadIdx.x & 31;
    if (warp >= N_NODES) return;

    float4 acc = reinterpret_cast<const float4*>(g_H + (size_t)warp * D)[lane];
    int beg = g_row_ofs[warp];
    int end = g_row_ofs[warp + 1];

    for (int base = beg; base < end; base += 32) {
        int idx = base + lane;
        int s = (idx < end) ? g_csr_src[idx] : 0;
        int cnt = min(32, end - base);
        for (int j = 0; j < cnt; j++) {
            int ss = __shfl_sync(0xffffffffu, s, j);
            float4 v = reinterpret_cast<const float4*>(g_H + (size_t)ss * D)[lane];
            acc.x += v.x; acc.y += v.y; acc.z += v.z; acc.w += v.w;
        }
    }

    float ni = rsqrtf((float)(end - beg + 1));
    int c0 = lane * 4;
    float x0 = acc.x * ni + g_bias[c0 + 0];
    float x1 = acc.y * ni + g_bias[c0 + 1];
    float x2 = acc.z * ni + g_bias[c0 + 2];
    float x3 = acc.w * ni + g_bias[c0 + 3];

    float s = x0 + x1 + x2 + x3;
    #pragma unroll
    for (int off = 16; off > 0; off >>= 1) s += __shfl_xor_sync(0xffffffffu, s, off);
    float mu = s * (1.0f / D);
    float d0 = x0 - mu, d1 = x1 - mu, d2 = x2 - mu, d3 = x3 - mu;
    float q = d0 * d0 + d1 * d1 + d2 * d2 + d3 * d3;
    #pragma unroll
    for (int off = 16; off > 0; off >>= 1) q += __shfl_xor_sync(0xffffffffu, q, off);
    float inv = rsqrtf(q * (1.0f / D) + 1e-5f);

    float4 o;
    o.x = fmaxf(d0 * inv * ln_g[c0 + 0] + ln_b[c0 + 0], 0.f);
    o.y = fmaxf(d1 * inv * ln_g[c0 + 1] + ln_b[c0 + 1], 0.f);
    o.z = fmaxf(d2 * inv * ln_g[c0 + 2] + ln_b[c0 + 2], 0.f);
    o.w = fmaxf(d3 * inv * ln_g[c0 + 3] + ln_b[c0 + 3], 0.f);
    reinterpret_cast<float4*>(out + (size_t)warp * D)[lane] = o;
}

// ---------------- launcher ----------------
extern "C" void kernel_launch(void* const* d_in, const int* in_sizes, int n_in,
                              void* d_out, int out_size) {
    const float* curr_h = (const float*)d_in[0];
    const float* next_h = (const float*)d_in[1];
    const float* inc    = (const float*)d_in[2];
    const int*   src    = (const int*)d_in[3];
    const int*   dst    = (const int*)d_in[4];
    const float* W_conv = (const float*)d_in[5];
    const float* b_conv = (const float*)d_in[6];
    const float* W_fus  = (const float*)d_in[7];
    const float* b_fus  = (const float*)d_in[8];
    const float* conv_w = (const float*)d_in[9];
    const float* tdw    = (const float*)d_in[10];
    const float* ln_g   = (const float*)d_in[11];
    const float* ln_b   = (const float*)d_in[12];
    float* out = (float*)d_out;
    const int E = in_sizes[3];

    k_init<<<(N_NODES + 255) / 256, 256>>>();
    k_count<<<(E + 255) / 256, 256>>>(src, dst, E);
    k_scan<<<1, 1024>>>(N_NODES);
    k_fill<<<(E + 255) / 256, 256>>>(src, dst, E);
    k_prepBias<<<1, 128>>>(b_conv, b_fus, conv_w, tdw);
    k_prepP<<<N_NEXT / 16, 128>>>(next_h, W_fus, tdw);
    k_packB<<<(NCH_TOT * CHUNK_FLOATS + 255) / 256, 256>>>(W_conv, conv_w);
    k_gemm_mma<<<(N_NODES + 127) / 128, 256>>>(curr_h, inc);
    k_gather<<<(N_NODES * 32 + 255) / 256, 256>>>(ln_g, ln_b, out);
}

// round 5
// speedup vs baseline: 3.0797x; 2.4233x over previous
#include <cuda_runtime.h>
#include <cstdint>

#define N_NODES 50000
#define N_NEXT  2000
#define D       128
#define E_MAX   1600000

#define KB        32
#define NCH_A     63                   // ceil(2000/32)
#define NCH_TOT   67                   // + 128/32 for curr_h phase
#define CHUNK_U32 2048                 // B frags: 2 ks * 16 j * 32 lanes * 2 regs (f16x2)

// ---------------- scratch ----------------
__device__ float    g_H[(size_t)N_NODES * D];
__device__ float    g_Pp[(size_t)N_NEXT * D];
__device__ uint32_t g_BF[(size_t)NCH_TOT * CHUNK_U32];   // B fp16 fragments
__device__ float    g_bias[D];
__device__ int      g_in_cnt[N_NODES];
__device__ int      g_out_cnt[N_NODES];
__device__ int      g_row_ofs[N_NODES + 1];
__device__ int      g_cursor[N_NODES];
__device__ int      g_csr_src[E_MAX];
__device__ int      g_blk[64];

// ---------------- helpers ----------------
__device__ __forceinline__ uint32_t smem_u32(const void* p) {
    uint32_t a;
    asm("{ .reg .u64 t; cvta.to.shared.u64 t, %1; cvt.u32.u64 %0, t; }" : "=r"(a) : "l"(p));
    return a;
}
__device__ __forceinline__ void cp16(uint32_t s, const void* g) {
    asm volatile("cp.async.cg.shared.global [%0], [%1], 16;" :: "r"(s), "l"(g) : "memory");
}
__device__ __forceinline__ uint32_t cvt2h(float lo, float hi) {
    uint32_t u;
    asm("cvt.rn.f16x2.f32 %0, %1, %2;" : "=r"(u) : "f"(hi), "f"(lo));  // 2nd src -> lo half
    return u;
}
__device__ __forceinline__ void mma16(float* c, const uint32_t* a, uint32_t b0, uint32_t b1) {
    asm volatile(
        "mma.sync.aligned.m16n8k16.row.col.f32.f16.f16.f32 "
        "{%0,%1,%2,%3}, {%4,%5,%6,%7}, {%8,%9}, {%0,%1,%2,%3};"
        : "+f"(c[0]), "+f"(c[1]), "+f"(c[2]), "+f"(c[3])
        : "r"(a[0]), "r"(a[1]), "r"(a[2]), "r"(a[3]), "r"(b0), "r"(b1));
}
__device__ __forceinline__ int clampi(int v, int lo, int hi) {
    return v < lo ? lo : (v > hi ? hi : v);
}

// ---------------- CSR build ----------------
__global__ void k_init() {
    int i = blockIdx.x * blockDim.x + threadIdx.x;
    if (i < N_NODES) { g_in_cnt[i] = 0; g_out_cnt[i] = 0; g_cursor[i] = 0; }
}

__global__ void k_count(const int* __restrict__ src, const int* __restrict__ dst, int E) {
    int e4 = (blockIdx.x * blockDim.x + threadIdx.x) * 4;
    if (e4 + 4 <= E) {
        int4 s = *reinterpret_cast<const int4*>(src + e4);
        int4 d = *reinterpret_cast<const int4*>(dst + e4);
        atomicAdd(&g_out_cnt[clampi(s.x, 0, N_NODES - 1)], 1);
        atomicAdd(&g_out_cnt[clampi(s.y, 0, N_NODES - 1)], 1);
        atomicAdd(&g_out_cnt[clampi(s.z, 0, N_NODES - 1)], 1);
        atomicAdd(&g_out_cnt[clampi(s.w, 0, N_NODES - 1)], 1);
        atomicAdd(&g_in_cnt[clampi(d.x, 0, N_NODES - 1)], 1);
        atomicAdd(&g_in_cnt[clampi(d.y, 0, N_NODES - 1)], 1);
        atomicAdd(&g_in_cnt[clampi(d.z, 0, N_NODES - 1)], 1);
        atomicAdd(&g_in_cnt[clampi(d.w, 0, N_NODES - 1)], 1);
    } else {
        for (int e = e4; e < E; e++) {
            atomicAdd(&g_out_cnt[clampi(src[e], 0, N_NODES - 1)], 1);
            atomicAdd(&g_in_cnt[clampi(dst[e], 0, N_NODES - 1)], 1);
        }
    }
}

__global__ void k_scan_a() {
    __shared__ int sh[1024];
    int b = blockIdx.x, t = threadIdx.x, i = b * 1024 + t;
    int v = (i < N_NODES) ? g_in_cnt[i] : 0;
    sh[t] = v;
    __syncthreads();
    for (int off = 1; off < 1024; off <<= 1) {
        int tv = (t >= off) ? sh[t - off] : 0;
        __syncthreads();
        sh[t] += tv;
        __syncthreads();
    }
    if (i < N_NODES) g_row_ofs[i] = sh[t] - v;
    if (t == 1023) g_blk[b] = sh[1023];
}
__global__ void k_scan_b() {
    __shared__ int sh[64];
    int t = threadIdx.x;
    int v = (t < 49) ? g_blk[t] : 0;
    sh[t] = v;
    __syncthreads();
    for (int off = 1; off < 64; off <<= 1) {
        int tv = (t >= off) ? sh[t - off] : 0;
        __syncthreads();
        sh[t] += tv;
        __syncthreads();
    }
    if (t < 49) g_blk[t] = sh[t] - v;
    if (t == 48) g_row_ofs[N_NODES] = sh[48];
}
__global__ void k_scan_c() {
    int b = blockIdx.x, i = b * 1024 + threadIdx.x;
    if (i < N_NODES && b > 0) g_row_ofs[i] += g_blk[b];
}

__global__ void k_fill(const int* __restrict__ src, const int* __restrict__ dst, int E) {
    int e = blockIdx.x * blockDim.x + threadIdx.x;
    if (e < E) {
        int d = clampi(dst[e], 0, N_NODES - 1);
        int pos = g_row_ofs[d] + atomicAdd(&g_cursor[d], 1);
        g_csr_src[pos] = clampi(src[e], 0, N_NODES - 1);
    }
}

// ---------------- prep: Pp = (next_h@W_fus)*tdw ; bias ----------------
__global__ void k_prepP(const float* __restrict__ next_h, const float* __restrict__ W_fus,
                        const float* __restrict__ tdw, const float* __restrict__ b_conv,
                        const float* __restrict__ b_fus, const float* __restrict__ conv_w) {
    __shared__ float sh[16][D];
    int r0 = blockIdx.x * 16;
    int j = threadIdx.x;
    if (blockIdx.x == 0) g_bias[j] = b_conv[j] * conv_w[j] + b_fus[j] * tdw[j];
    #pragma unroll
    for (int r = 0; r < 16; r++) sh[r][j] = next_h[(r0 + r) * D + j];
    __syncthreads();
    float acc[16];
    #pragma unroll
    for (int r = 0; r < 16; r++) acc[r] = 0.f;
    for (int k = 0; k < D; k++) {
        float w = W_fus[k * D + j];
        #pragma unroll
        for (int r = 0; r < 16; r++) acc[r] += sh[r][k] * w;
    }
    float t = tdw[j];
    #pragma unroll
    for (int r = 0; r < 16; r++) g_Pp[(size_t)(r0 + r) * D + j] = acc[r] * t;
}

// pack B into m16n8k16 fp16 fragment order, one 8KB chunk per K-block of 32.
// index in chunk = ((ks*16 + j)*32 + lane)*2 + e ; lane=(g<<2)|tg
// value = {B[k0+ks*16+2tg+8e][j*8+g] (lo), B[..+1][..] (hi)}
__global__ void k_packB(const float* __restrict__ W_conv, const float* __restrict__ conv_w) {
    int i = blockIdx.x * blockDim.x + threadIdx.x;
    if (i >= NCH_TOT * CHUNK_U32) return;
    int c = i >> 11, rem = i & 2047;
    int e = rem & 1;
    int lane = (rem >> 1) & 31;
    int j = (rem >> 6) & 15;
    int ks = rem >> 10;
    int g = lane >> 2, tg = lane & 3;
    int n = j * 8 + g;
    int kl = ks * 16 + 2 * tg + e * 8;
    float v0, v1;
    if (c < NCH_A) {
        int kg = c * KB + kl;
        v0 = (kg < N_NEXT) ? g_Pp[(size_t)kg * D + n] : 0.f;
        v1 = (kg + 1 < N_NEXT) ? g_Pp[(size_t)(kg + 1) * D + n] : 0.f;
    } else {
        int kg = (c - NCH_A) * KB + kl;
        v0 = W_conv[kg * D + n] * conv_w[n];
        v1 = W_conv[(kg + 1) * D + n] * conv_w[n];
    }
    g_BF[i] = cvt2h(v0, v1);
}

// ---------------- fp16 mma GEMM: H = norm_out .* (inc@Pp + curr_h@Wcp) ----------------
// block: 128 threads (4 warps), M=128 (32 rows/warp = 2 m16 tiles), N=128, K-chunk 32.
#define ASTRIDE 40
#define A_TILE_F (128 * ASTRIDE)                 // floats per stage
__global__ __launch_bounds__(128, 2) void k_gemm(const float* __restrict__ curr_h,
                                                 const float* __restrict__ inc) {
    extern __shared__ char smem[];
    float*    sA = reinterpret_cast<float*>(smem);                      // [2][128*40]
    uint32_t* sB = reinterpret_cast<uint32_t*>(smem + 2 * A_TILE_F * 4);// [2][2048]
    const int tid = threadIdx.x, wid = tid >> 5, lane = tid & 31;
    const int g = lane >> 2, tg = lane & 3;
    const int bm = blockIdx.x * 128;

    float acc[2][16][4];
    #pragma unroll
    for (int mt = 0; mt < 2; mt++)
        #pragma unroll
        for (int j = 0; j < 16; j++)
            #pragma unroll
            for (int q = 0; q < 4; q++) acc[mt][j][q] = 0.f;

    auto fetch = [&](int c, int buf) {
        const float* Ap; int ld, k0;
        if (c < NCH_A) { Ap = inc; ld = N_NEXT; k0 = c * KB; }
        else           { Ap = curr_h; ld = D; k0 = (c - NCH_A) * KB; }
        #pragma unroll
        for (int q8 = 0; q8 < 8; q8++) {
            int idx = q8 * 128 + tid;
            int row = idx >> 3, quad = idx & 7;
            int grow = bm + row;
            if (grow >= N_NODES) grow = N_NODES - 1;
            int col = k0 + quad * 4;
            float* dstp = sA + buf * A_TILE_F + row * ASTRIDE + quad * 4;
            if (col + 4 <= ld) cp16(smem_u32(dstp), Ap + (size_t)grow * ld + col);
            else *reinterpret_cast<float4*>(dstp) = make_float4(0.f, 0.f, 0.f, 0.f);
        }
        const uint32_t* srcb = g_BF + (size_t)c * CHUNK_U32 + tid * 16;
        uint32_t dstb = smem_u32(sB + buf * CHUNK_U32 + tid * 16);
        cp16(dstb, srcb); cp16(dstb + 16, srcb + 4);
        cp16(dstb + 32, srcb + 8); cp16(dstb + 48, srcb + 12);
        asm volatile("cp.async.commit_group;" ::: "memory");
    };

    auto compute = [&](int buf) {
        const float* sa = sA + buf * A_TILE_F;
        const uint32_t* sb = sB + buf * CHUNK_U32;
        #pragma unroll
        for (int ks = 0; ks < 2; ks++) {
            uint32_t af[2][4];
            #pragma unroll
            for (int mt = 0; mt < 2; mt++) {
                const float* base = sa + (wid * 32 + mt * 16) * ASTRIDE + ks * 16 + 2 * tg;
                float2 p0 = *reinterpret_cast<const float2*>(base + g * ASTRIDE);
                float2 p1 = *reinterpret_cast<const float2*>(base + (g + 8) * ASTRIDE);
                float2 p2 = *reinterpret_cast<const float2*>(base + g * ASTRIDE + 8);
                float2 p3 = *reinterpret_cast<const float2*>(base + (g + 8) * ASTRIDE + 8);
                af[mt][0] = cvt2h(p0.x, p0.y);
                af[mt][1] = cvt2h(p1.x, p1.y);
                af[mt][2] = cvt2h(p2.x, p2.y);
                af[mt][3] = cvt2h(p3.x, p3.y);
            }
            #pragma unroll
            for (int j = 0; j < 16; j++) {
                uint2 b = *reinterpret_cast<const uint2*>(sb + (ks * 16 + j) * 64 + lane * 2);
                mma16(acc[0][j], af[0], b.x, b.y);
                mma16(acc[1][j], af[1], b.x, b.y);
            }
        }
    };

    fetch(0, 0);
    for (int c = 0; c < NCH_TOT; ++c) {
        const int cb = c & 1;
        if (c + 1 < NCH_TOT) {
            fetch(c + 1, cb ^ 1);
            asm volatile("cp.async.wait_group 1;" ::: "memory");
        } else {
            asm volatile("cp.async.wait_group 0;" ::: "memory");
        }
        __syncthreads();
        compute(cb);
        __syncthreads();
    }

    // epilogue: apply norm_out, write H
    #pragma unroll
    for (int mt = 0; mt < 2; mt++) {
        int r0 = bm + wid * 32 + mt * 16 + g;
        int r1 = r0 + 8;
        if (r0 < N_NODES) {
            float no = rsqrtf((float)(g_out_cnt[r0] + 1));
            float* dp = g_H + (size_t)r0 * D + 2 * tg;
            #pragma unroll
            for (int j = 0; j < 16; j++)
                *reinterpret_cast<float2*>(dp + j * 8) =
                    make_float2(acc[mt][j][0] * no, acc[mt][j][1] * no);
        }
        if (r1 < N_NODES) {
            float no = rsqrtf((float)(g_out_cnt[r1] + 1));
            float* dp = g_H + (size_t)r1 * D + 2 * tg;
            #pragma unroll
            for (int j = 0; j < 16; j++)
                *reinterpret_cast<float2*>(dp + j * 8) =
                    make_float2(acc[mt][j][2] * no, acc[mt][j][3] * no);
        }
    }
}
#define GEMM_SMEM (2 * A_TILE_F * 4 + 2 * CHUNK_U32 * 4)

// ---------------- gather + norm_in + bias + LayerNorm + ReLU ----------------
__global__ void k_gather(const float* __restrict__ ln_g, const float* __restrict__ ln_b,
                         float* __restrict__ out) {
    int warp = (blockIdx.x * blockDim.x + threadIdx.x) >> 5;
    int lane = threadIdx.x & 31;
    if (warp >= N_NODES) return;

    float4 a0 = reinterpret_cast<const float4*>(g_H + (size_t)warp * D)[lane];
    float4 a1 = make_float4(0.f, 0.f, 0.f, 0.f), a2 = a1, a3 = a1;
    int beg = g_row_ofs[warp];
    int end = g_row_ofs[warp + 1];

    int j = beg;
    for (; j + 4 <= end; j += 4) {
        int s0 = __ldg(g_csr_src + j);
        int s1 = __ldg(g_csr_src + j + 1);
        int s2 = __ldg(g_csr_src + j + 2);
        int s3 = __ldg(g_csr_src + j + 3);
        float4 v0 = reinterpret_cast<const float4*>(g_H + (size_t)s0 * D)[lane];
        float4 v1 = reinterpret_cast<const float4*>(g_H + (size_t)s1 * D)[lane];
        float4 v2 = reinterpret_cast<const float4*>(g_H + (size_t)s2 * D)[lane];
        float4 v3 = reinterpret_cast<const float4*>(g_H + (size_t)s3 * D)[lane];
        a0.x += v0.x; a0.y += v0.y; a0.z += v0.z; a0.w += v0.w;
        a1.x += v1.x; a1.y += v1.y; a1.z += v1.z; a1.w += v1.w;
        a2.x += v2.x; a2.y += v2.y; a2.z += v2.z; a2.w += v2.w;
        a3.x += v3.x; a3.y += v3.y; a3.z += v3.z; a3.w += v3.w;
    }
    for (; j < end; j++) {
        int s = __ldg(g_csr_src + j);
        float4 v = reinterpret_cast<const float4*>(g_H + (size_t)s * D)[lane];
        a0.x += v.x; a0.y += v.y; a0.z += v.z; a0.w += v.w;
    }
    float4 acc;
    acc.x = (a0.x + a1.x) + (a2.x + a3.x);
    acc.y = (a0.y + a1.y) + (a2.y + a3.y);
    acc.z = (a0.z + a1.z) + (a2.z + a3.z);
    acc.w = (a0.w + a1.w) + (a2.w + a3.w);

    float ni = rsqrtf((float)(end - beg + 1));
    int c0 = lane * 4;
    float x0 = acc.x * ni + g_bias[c0 + 0];
    float x1 = acc.y * ni + g_bias[c0 + 1];
    float x2 = acc.z * ni + g_bias[c0 + 2];
    float x3 = acc.w * ni + g_bias[c0 + 3];

    float s = x0 + x1 + x2 + x3;
    #pragma unroll
    for (int off = 16; off > 0; off >>= 1) s += __shfl_xor_sync(0xffffffffu, s, off);
    float mu = s * (1.0f / D);
    float d0 = x0 - mu, d1 = x1 - mu, d2 = x2 - mu, d3 = x3 - mu;
    float q = d0 * d0 + d1 * d1 + d2 * d2 + d3 * d3;
    #pragma unroll
    for (int off = 16; off > 0; off >>= 1) q += __shfl_xor_sync(0xffffffffu, q, off);
    float inv = rsqrtf(q * (1.0f / D) + 1e-5f);

    float4 o;
    o.x = fmaxf(d0 * inv * ln_g[c0 + 0] + ln_b[c0 + 0], 0.f);
    o.y = fmaxf(d1 * inv * ln_g[c0 + 1] + ln_b[c0 + 1], 0.f);
    o.z = fmaxf(d2 * inv * ln_g[c0 + 2] + ln_b[c0 + 2], 0.f);
    o.w = fmaxf(d3 * inv * ln_g[c0 + 3] + ln_b[c0 + 3], 0.f);
    reinterpret_cast<float4*>(out + (size_t)warp * D)[lane] = o;
}

// ---------------- launcher ----------------
extern "C" void kernel_launch(void* const* d_in, const int* in_sizes, int n_in,
                              void* d_out, int out_size) {
    const float* curr_h = (const float*)d_in[0];
    const float* next_h = (const float*)d_in[1];
    const float* inc    = (const float*)d_in[2];
    const int*   src    = (const int*)d_in[3];
    const int*   dst    = (const int*)d_in[4];
    const float* W_conv = (const float*)d_in[5];
    const float* b_conv = (const float*)d_in[6];
    const float* W_fus  = (const float*)d_in[7];
    const float* b_fus  = (const float*)d_in[8];
    const float* conv_w = (const float*)d_in[9];
    const float* tdw    = (const float*)d_in[10];
    const float* ln_g   = (const float*)d_in[11];
    const float* ln_b   = (const float*)d_in[12];
    float* out = (float*)d_out;
    const int E = in_sizes[3];

    static bool attr_set = false;
    if (!attr_set) {
        cudaFuncSetAttribute(k_gemm, cudaFuncAttributeMaxDynamicSharedMemorySize, GEMM_SMEM);
        attr_set = true;
    }

    k_init<<<(N_NODES + 255) / 256, 256>>>();
    k_count<<<(E / 4 + 255) / 256, 256>>>(src, dst, E);
    k_prepP<<<N_NEXT / 16, 128>>>(next_h, W_fus, tdw, b_conv, b_fus, conv_w);
    k_packB<<<(NCH_TOT * CHUNK_U32 + 255) / 256, 256>>>(W_conv, conv_w);
    k_gemm<<<(N_NODES + 127) / 128, 128, GEMM_SMEM>>>(curr_h, inc);
    k_scan_a<<<49, 1024>>>();
    k_scan_b<<<1, 64>>>();
    k_scan_c<<<49, 1024>>>();
    k_fill<<<(E + 255) / 256, 256>>>(src, dst, E);
    k_gather<<<(N_NODES * 32 + 255) / 256, 256>>>(ln_g, ln_b, out);
}

// round 6
// speedup vs baseline: 3.1818x; 1.0331x over previous
#include <cuda_runtime.h>
#include <cuda_fp16.h>
#include <cstdint>

#define N_NODES 50000
#define N_NEXT  2000
#define D       128
#define E_MAX   1600000

#define KB        32
#define NCH_A     63                   // ceil(2000/32)
#define NCH_TOT   67                   // + 128/32 for curr_h phase
#define CHUNK_U32 2048                 // B frags: 2 ks * 16 j * 32 lanes * 2 regs (f16x2)

// ---------------- scratch ----------------
__device__ __half2  g_Hh[(size_t)N_NODES * 64];          // H in fp16 (64 half2 per row)
__device__ float    g_Pp[(size_t)N_NEXT * D];
__device__ uint32_t g_BF[(size_t)NCH_TOT * CHUNK_U32];   // B fp16 fragments
__device__ float    g_bias[D];
__device__ int      g_in_cnt[N_NODES];
__device__ int      g_out_cnt[N_NODES];
__device__ int      g_row_ofs[N_NODES + 1];
__device__ int      g_cursor[N_NODES];
__device__ int      g_csr_src[E_MAX];
__device__ int      g_blk[64];

// ---------------- helpers ----------------
__device__ __forceinline__ uint32_t smem_u32(const void* p) {
    uint32_t a;
    asm("{ .reg .u64 t; cvta.to.shared.u64 t, %1; cvt.u32.u64 %0, t; }" : "=r"(a) : "l"(p));
    return a;
}
__device__ __forceinline__ void cp16(uint32_t s, const void* g) {
    asm volatile("cp.async.cg.shared.global [%0], [%1], 16;" :: "r"(s), "l"(g) : "memory");
}
__device__ __forceinline__ uint32_t cvt2h(float lo, float hi) {
    uint32_t u;
    asm("cvt.rn.f16x2.f32 %0, %1, %2;" : "=r"(u) : "f"(hi), "f"(lo));  // 2nd src -> lo half
    return u;
}
__device__ __forceinline__ void mma16(float* c, const uint32_t* a, uint32_t b0, uint32_t b1) {
    asm volatile(
        "mma.sync.aligned.m16n8k16.row.col.f32.f16.f16.f32 "
        "{%0,%1,%2,%3}, {%4,%5,%6,%7}, {%8,%9}, {%0,%1,%2,%3};"
        : "+f"(c[0]), "+f"(c[1]), "+f"(c[2]), "+f"(c[3])
        : "r"(a[0]), "r"(a[1]), "r"(a[2]), "r"(a[3]), "r"(b0), "r"(b1));
}
__device__ __forceinline__ int clampi(int v, int lo, int hi) {
    return v < lo ? lo : (v > hi ? hi : v);
}
// load 4 fp32 values (cols lane*4..lane*4+3) from fp16 row, accumulate into f4
__device__ __forceinline__ void accH(float4& a, const __half2* rowp, int lane) {
    uint2 u = *reinterpret_cast<const uint2*>(rowp + lane * 2);
    __half2 h0 = *reinterpret_cast<__half2*>(&u.x);
    __half2 h1 = *reinterpret_cast<__half2*>(&u.y);
    float2 f0 = __half22float2(h0);
    float2 f1 = __half22float2(h1);
    a.x += f0.x; a.y += f0.y; a.z += f1.x; a.w += f1.y;
}

// ---------------- CSR build ----------------
__global__ void k_count(const int* __restrict__ src, const int* __restrict__ dst, int E) {
    int e4 = (blockIdx.x * blockDim.x + threadIdx.x) * 4;
    if (e4 + 4 <= E) {
        int4 s = *reinterpret_cast<const int4*>(src + e4);
        int4 d = *reinterpret_cast<const int4*>(dst + e4);
        atomicAdd(&g_out_cnt[clampi(s.x, 0, N_NODES - 1)], 1);
        atomicAdd(&g_out_cnt[clampi(s.y, 0, N_NODES - 1)], 1);
        atomicAdd(&g_out_cnt[clampi(s.z, 0, N_NODES - 1)], 1);
        atomicAdd(&g_out_cnt[clampi(s.w, 0, N_NODES - 1)], 1);
        atomicAdd(&g_in_cnt[clampi(d.x, 0, N_NODES - 1)], 1);
        atomicAdd(&g_in_cnt[clampi(d.y, 0, N_NODES - 1)], 1);
        atomicAdd(&g_in_cnt[clampi(d.z, 0, N_NODES - 1)], 1);
        atomicAdd(&g_in_cnt[clampi(d.w, 0, N_NODES - 1)], 1);
    } else {
        for (int e = e4; e < E; e++) {
            atomicAdd(&g_out_cnt[clampi(src[e], 0, N_NODES - 1)], 1);
            atomicAdd(&g_in_cnt[clampi(dst[e], 0, N_NODES - 1)], 1);
        }
    }
}

__global__ void k_scan_a() {
    __shared__ int sh[1024];
    int b = blockIdx.x, t = threadIdx.x, i = b * 1024 + t;
    int v = (i < N_NODES) ? g_in_cnt[i] : 0;
    sh[t] = v;
    __syncthreads();
    for (int off = 1; off < 1024; off <<= 1) {
        int tv = (t >= off) ? sh[t - off] : 0;
        __syncthreads();
        sh[t] += tv;
        __syncthreads();
    }
    if (i < N_NODES) g_row_ofs[i] = sh[t] - v;
    if (t == 1023) g_blk[b] = sh[1023];
}
__global__ void k_scan_b() {
    __shared__ int sh[64];
    int t = threadIdx.x;
    int v = (t < 49) ? g_blk[t] : 0;
    sh[t] = v;
    __syncthreads();
    for (int off = 1; off < 64; off <<= 1) {
        int tv = (t >= off) ? sh[t - off] : 0;
        __syncthreads();
        sh[t] += tv;
        __syncthreads();
    }
    if (t < 49) g_blk[t] = sh[t] - v;
    if (t == 48) g_row_ofs[N_NODES] = sh[48];
}
__global__ void k_scan_c() {
    int b = blockIdx.x, i = b * 1024 + threadIdx.x;
    if (i < N_NODES && b > 0) g_row_ofs[i] += g_blk[b];
}

__global__ void k_fill(const int* __restrict__ src, const int* __restrict__ dst, int E) {
    int e4 = (blockIdx.x * blockDim.x + threadIdx.x) * 4;
    if (e4 + 4 <= E) {
        int4 s = *reinterpret_cast<const int4*>(src + e4);
        int4 d = *reinterpret_cast<const int4*>(dst + e4);
        int dd, pos;
        dd = clampi(d.x, 0, N_NODES - 1);
        pos = g_row_ofs[dd] + atomicAdd(&g_cursor[dd], 1);
        g_csr_src[pos] = clampi(s.x, 0, N_NODES - 1);
        dd = clampi(d.y, 0, N_NODES - 1);
        pos = g_row_ofs[dd] + atomicAdd(&g_cursor[dd], 1);
        g_csr_src[pos] = clampi(s.y, 0, N_NODES - 1);
        dd = clampi(d.z, 0, N_NODES - 1);
        pos = g_row_ofs[dd] + atomicAdd(&g_cursor[dd], 1);
        g_csr_src[pos] = clampi(s.z, 0, N_NODES - 1);
        dd = clampi(d.w, 0, N_NODES - 1);
        pos = g_row_ofs[dd] + atomicAdd(&g_cursor[dd], 1);
        g_csr_src[pos] = clampi(s.w, 0, N_NODES - 1);
    } else {
        for (int e = e4; e < E; e++) {
            int dd = clampi(dst[e], 0, N_NODES - 1);
            int pos = g_row_ofs[dd] + atomicAdd(&g_cursor[dd], 1);
            g_csr_src[pos] = clampi(src[e], 0, N_NODES - 1);
        }
    }
}

// ---------------- prep: Pp = (next_h@W_fus)*tdw ; bias ----------------
__global__ void k_prepP(const float* __restrict__ next_h, const float* __restrict__ W_fus,
                        const float* __restrict__ tdw, const float* __restrict__ b_conv,
                        const float* __restrict__ b_fus, const float* __restrict__ conv_w) {
    __shared__ float sh[16][D];
    int r0 = blockIdx.x * 16;
    int j = threadIdx.x;
    if (blockIdx.x == 0) g_bias[j] = b_conv[j] * conv_w[j] + b_fus[j] * tdw[j];
    #pragma unroll
    for (int r = 0; r < 16; r++) sh[r][j] = next_h[(r0 + r) * D + j];
    __syncthreads();
    float acc[16];
    #pragma unroll
    for (int r = 0; r < 16; r++) acc[r] = 0.f;
    for (int k = 0; k < D; k++) {
        float w = W_fus[k * D + j];
        #pragma unroll
        for (int r = 0; r < 16; r++) acc[r] += sh[r][k] * w;
    }
    float t = tdw[j];
    #pragma unroll
    for (int r = 0; r < 16; r++) g_Pp[(size_t)(r0 + r) * D + j] = acc[r] * t;
}

// pack B into m16n8k16 fp16 fragment order, one 8KB chunk per K-block of 32.
__global__ void k_packB(const float* __restrict__ W_conv, const float* __restrict__ conv_w) {
    int i = blockIdx.x * blockDim.x + threadIdx.x;
    if (i >= NCH_TOT * CHUNK_U32) return;
    int c = i >> 11, rem = i & 2047;
    int e = rem & 1;
    int lane = (rem >> 1) & 31;
    int j = (rem >> 6) & 15;
    int ks = rem >> 10;
    int g = lane >> 2, tg = lane & 3;
    int n = j * 8 + g;
    int kl = ks * 16 + 2 * tg + e * 8;
    float v0, v1;
    if (c < NCH_A) {
        int kg = c * KB + kl;
        v0 = (kg < N_NEXT) ? g_Pp[(size_t)kg * D + n] : 0.f;
        v1 = (kg + 1 < N_NEXT) ? g_Pp[(size_t)(kg + 1) * D + n] : 0.f;
    } else {
        int kg = (c - NCH_A) * KB + kl;
        v0 = W_conv[kg * D + n] * conv_w[n];
        v1 = W_conv[(kg + 1) * D + n] * conv_w[n];
    }
    g_BF[i] = cvt2h(v0, v1);
}

// ---------------- fp16 mma GEMM: H = norm_out .* (inc@Pp + curr_h@Wcp) -> fp16 ----------------
#define ASTRIDE 40
#define A_TILE_F (128 * ASTRIDE)
__global__ __launch_bounds__(128, 2) void k_gemm(const float* __restrict__ curr_h,
                                                 const float* __restrict__ inc) {
    extern __shared__ char smem[];
    float*    sA = reinterpret_cast<float*>(smem);                       // [2][128*40]
    uint32_t* sB = reinterpret_cast<uint32_t*>(smem + 2 * A_TILE_F * 4); // [2][2048]
    const int tid = threadIdx.x, wid = tid >> 5, lane = tid & 31;
    const int g = lane >> 2, tg = lane & 3;
    const int bm = blockIdx.x * 128;

    float acc[2][16][4];
    #pragma unroll
    for (int mt = 0; mt < 2; mt++)
        #pragma unroll
        for (int j = 0; j < 16; j++)
            #pragma unroll
            for (int q = 0; q < 4; q++) acc[mt][j][q] = 0.f;

    auto fetch = [&](int c, int buf) {
        const float* Ap; int ld, k0;
        if (c < NCH_A) { Ap = inc; ld = N_NEXT; k0 = c * KB; }
        else           { Ap = curr_h; ld = D; k0 = (c - NCH_A) * KB; }
        #pragma unroll
        for (int q8 = 0; q8 < 8; q8++) {
            int idx = q8 * 128 + tid;
            int row = idx >> 3, quad = idx & 7;
            int grow = bm + row;
            if (grow >= N_NODES) grow = N_NODES - 1;
            int col = k0 + quad * 4;
            float* dstp = sA + buf * A_TILE_F + row * ASTRIDE + quad * 4;
            if (col + 4 <= ld) cp16(smem_u32(dstp), Ap + (size_t)grow * ld + col);
            else *reinterpret_cast<float4*>(dstp) = make_float4(0.f, 0.f, 0.f, 0.f);
        }
        const uint32_t* srcb = g_BF + (size_t)c * CHUNK_U32 + tid * 16;
        uint32_t dstb = smem_u32(sB + buf * CHUNK_U32 + tid * 16);
        cp16(dstb, srcb); cp16(dstb + 16, srcb + 4);
        cp16(dstb + 32, srcb + 8); cp16(dstb + 48, srcb + 12);
        asm volatile("cp.async.commit_group;" ::: "memory");
    };

    auto compute = [&](int buf) {
        const float* sa = sA + buf * A_TILE_F;
        const uint32_t* sb = sB + buf * CHUNK_U32;
        #pragma unroll
        for (int ks = 0; ks < 2; ks++) {
            uint32_t af[2][4];
            #pragma unroll
            for (int mt = 0; mt < 2; mt++) {
                const float* base = sa + (wid * 32 + mt * 16) * ASTRIDE + ks * 16 + 2 * tg;
                float2 p0 = *reinterpret_cast<const float2*>(base + g * ASTRIDE);
                float2 p1 = *reinterpret_cast<const float2*>(base + (g + 8) * ASTRIDE);
                float2 p2 = *reinterpret_cast<const float2*>(base + g * ASTRIDE + 8);
                float2 p3 = *reinterpret_cast<const float2*>(base + (g + 8) * ASTRIDE + 8);
                af[mt][0] = cvt2h(p0.x, p0.y);
                af[mt][1] = cvt2h(p1.x, p1.y);
                af[mt][2] = cvt2h(p2.x, p2.y);
                af[mt][3] = cvt2h(p3.x, p3.y);
            }
            #pragma unroll
            for (int j = 0; j < 16; j++) {
                uint2 b = *reinterpret_cast<const uint2*>(sb + (ks * 16 + j) * 64 + lane * 2);
                mma16(acc[0][j], af[0], b.x, b.y);
                mma16(acc[1][j], af[1], b.x, b.y);
            }
        }
    };

    fetch(0, 0);
    for (int c = 0; c < NCH_TOT; ++c) {
        const int cb = c & 1;
        if (c + 1 < NCH_TOT) {
            fetch(c + 1, cb ^ 1);
            asm volatile("cp.async.wait_group 1;" ::: "memory");
        } else {
            asm volatile("cp.async.wait_group 0;" ::: "memory");
        }
        __syncthreads();
        compute(cb);
        __syncthreads();
    }

    // epilogue: apply norm_out, convert to fp16, write H
    #pragma unroll
    for (int mt = 0; mt < 2; mt++) {
        int r0 = bm + wid * 32 + mt * 16 + g;
        int r1 = r0 + 8;
        if (r0 < N_NODES) {
            float no = rsqrtf((float)(g_out_cnt[r0] + 1));
            __half2* dp = g_Hh + (size_t)r0 * 64 + tg;
            #pragma unroll
            for (int j = 0; j < 16; j++)
                dp[j * 4] = __floats2half2_rn(acc[mt][j][0] * no, acc[mt][j][1] * no);
        }
        if (r1 < N_NODES) {
            float no = rsqrtf((float)(g_out_cnt[r1] + 1));
            __half2* dp = g_Hh + (size_t)r1 * 64 + tg;
            #pragma unroll
            for (int j = 0; j < 16; j++)
                dp[j * 4] = __floats2half2_rn(acc[mt][j][2] * no, acc[mt][j][3] * no);
        }
    }
}
#define GEMM_SMEM (2 * A_TILE_F * 4 + 2 * CHUNK_U32 * 4)

// ---------------- gather + norm_in + bias + LayerNorm + ReLU ----------------
__global__ void k_gather(const float* __restrict__ ln_g, const float* __restrict__ ln_b,
                         float* __restrict__ out) {
    int warp = (blockIdx.x * blockDim.x + threadIdx.x) >> 5;
    int lane = threadIdx.x & 31;
    if (warp >= N_NODES) return;

    float4 a0 = make_float4(0.f, 0.f, 0.f, 0.f), a1 = a0, a2 = a0, a3 = a0;
    accH(a0, g_Hh + (size_t)warp * 64, lane);       // self-loop
    int beg = g_row_ofs[warp];
    int end = g_row_ofs[warp + 1];

    int j = beg;
    for (; j + 4 <= end; j += 4) {
        int s0 = __ldg(g_csr_src + j);
        int s1 = __ldg(g_csr_src + j + 1);
        int s2 = __ldg(g_csr_src + j + 2);
        int s3 = __ldg(g_csr_src + j + 3);
        accH(a0, g_Hh + (size_t)s0 * 64, lane);
        accH(a1, g_Hh + (size_t)s1 * 64, lane);
        accH(a2, g_Hh + (size_t)s2 * 64, lane);
        accH(a3, g_Hh + (size_t)s3 * 64, lane);
    }
    for (; j < end; j++) {
        int s = __ldg(g_csr_src + j);
        accH(a0, g_Hh + (size_t)s * 64, lane);
    }
    float4 acc;
    acc.x = (a0.x + a1.x) + (a2.x + a3.x);
    acc.y = (a0.y + a1.y) + (a2.y + a3.y);
    acc.z = (a0.z + a1.z) + (a2.z + a3.z);
    acc.w = (a0.w + a1.w) + (a2.w + a3.w);

    float ni = rsqrtf((float)(end - beg + 1));
    int c0 = lane * 4;
    float x0 = acc.x * ni + g_bias[c0 + 0];
    float x1 = acc.y * ni + g_bias[c0 + 1];
    float x2 = acc.z * ni + g_bias[c0 + 2];
    float x3 = acc.w * ni + g_bias[c0 + 3];

    float s = x0 + x1 + x2 + x3;
    #pragma unroll
    for (int off = 16; off > 0; off >>= 1) s += __shfl_xor_sync(0xffffffffu, s, off);
    float mu = s * (1.0f / D);
    float d0 = x0 - mu, d1 = x1 - mu, d2 = x2 - mu, d3 = x3 - mu;
    float q = d0 * d0 + d1 * d1 + d2 * d2 + d3 * d3;
    #pragma unroll
    for (int off = 16; off > 0; off >>= 1) q += __shfl_xor_sync(0xffffffffu, q, off);
    float inv = rsqrtf(q * (1.0f / D) + 1e-5f);

    float4 o;
    o.x = fmaxf(d0 * inv * ln_g[c0 + 0] + ln_b[c0 + 0], 0.f);
    o.y = fmaxf(d1 * inv * ln_g[c0 + 1] + ln_b[c0 + 1], 0.f);
    o.z = fmaxf(d2 * inv * ln_g[c0 + 2] + ln_b[c0 + 2], 0.f);
    o.w = fmaxf(d3 * inv * ln_g[c0 + 3] + ln_b[c0 + 3], 0.f);
    reinterpret_cast<float4*>(out + (size_t)warp * D)[lane] = o;
}

// ---------------- launcher ----------------
extern "C" void kernel_launch(void* const* d_in, const int* in_sizes, int n_in,
                              void* d_out, int out_size) {
    const float* curr_h = (const float*)d_in[0];
    const float* next_h = (const float*)d_in[1];
    const float* inc    = (const float*)d_in[2];
    const int*   src    = (const int*)d_in[3];
    const int*   dst    = (const int*)d_in[4];
    const float* W_conv = (const float*)d_in[5];
    const float* b_conv = (const float*)d_in[6];
    const float* W_fus  = (const float*)d_in[7];
    const float* b_fus  = (const float*)d_in[8];
    const float* conv_w = (const float*)d_in[9];
    const float* tdw    = (const float*)d_in[10];
    const float* ln_g   = (const float*)d_in[11];
    const float* ln_b   = (const float*)d_in[12];
    float* out = (float*)d_out;
    const int E = in_sizes[3];

    static bool attr_set = false;
    if (!attr_set) {
        cudaFuncSetAttribute(k_gemm, cudaFuncAttributeMaxDynamicSharedMemorySize, GEMM_SMEM);
        attr_set = true;
    }

    void *p_in, *p_out, *p_cur;
    cudaGetSymbolAddress(&p_in, g_in_cnt);
    cudaGetSymbolAddress(&p_out, g_out_cnt);
    cudaGetSymbolAddress(&p_cur, g_cursor);
    cudaMemsetAsync(p_in, 0, N_NODES * sizeof(int));
    cudaMemsetAsync(p_out, 0, N_NODES * sizeof(int));
    cudaMemsetAsync(p_cur, 0, N_NODES * sizeof(int));

    k_count<<<(E / 4 + 255) / 256, 256>>>(src, dst, E);
    k_prepP<<<N_NEXT / 16, 128>>>(next_h, W_fus, tdw, b_conv, b_fus, conv_w);
    k_packB<<<(NCH_TOT * CHUNK_U32 + 255) / 256, 256>>>(W_conv, conv_w);
    k_gemm<<<(N_NODES + 127) / 128, 128, GEMM_SMEM>>>(curr_h, inc);
    k_scan_a<<<49, 1024>>>();
    k_scan_b<<<1, 64>>>();
    k_scan_c<<<49, 1024>>>();
    k_fill<<<(E + 1023) / 1024, 256>>>(src, dst, E);
    k_gather<<<(N_NODES * 32 + 255) / 256, 256>>>(ln_g, ln_b, out);
}

// round 7
// speedup vs baseline: 3.5258x; 1.1081x over previous
#include <cuda_runtime.h>
#include <cuda_fp16.h>
#include <cstdint>

#define N_NODES 50000
#define N_NEXT  2000
#define D       128
#define E_MAX   1600000

#define KB        32
#define NCH_A     63                   // ceil(2000/32)
#define NCH_TOT   67                   // + 128/32 for curr_h phase
#define CHUNK_U32 2048                 // B frags: 2 ks * 16 j * 32 lanes * 2 regs (f16x2)

// ---------------- scratch ----------------
__device__ __half2  g_Hh[(size_t)N_NODES * 64];          // H in fp16 (64 half2 per row)
__device__ float    g_Pp[(size_t)N_NEXT * D];
__device__ uint32_t g_BF[(size_t)NCH_TOT * CHUNK_U32];   // B fp16 fragments
__device__ float    g_bias[D];
__device__ int      g_in_cnt[N_NODES];
__device__ int      g_out_cnt[N_NODES];
__device__ int      g_row_ofs[N_NODES + 1];
__device__ int      g_csr_src[E_MAX];
__device__ int      g_blk[64];

// ---------------- helpers ----------------
__device__ __forceinline__ uint32_t smem_u32(const void* p) {
    uint32_t a;
    asm("{ .reg .u64 t; cvta.to.shared.u64 t, %1; cvt.u32.u64 %0, t; }" : "=r"(a) : "l"(p));
    return a;
}
__device__ __forceinline__ void cp16(uint32_t s, const void* g) {
    asm volatile("cp.async.cg.shared.global [%0], [%1], 16;" :: "r"(s), "l"(g) : "memory");
}
__device__ __forceinline__ uint32_t cvt2h(float lo, float hi) {
    uint32_t u;
    asm("cvt.rn.f16x2.f32 %0, %1, %2;" : "=r"(u) : "f"(hi), "f"(lo));  // 2nd src -> lo half
    return u;
}
__device__ __forceinline__ void mma16(float* c, const uint32_t* a, uint32_t b0, uint32_t b1) {
    asm volatile(
        "mma.sync.aligned.m16n8k16.row.col.f32.f16.f16.f32 "
        "{%0,%1,%2,%3}, {%4,%5,%6,%7}, {%8,%9}, {%0,%1,%2,%3};"
        : "+f"(c[0]), "+f"(c[1]), "+f"(c[2]), "+f"(c[3])
        : "r"(a[0]), "r"(a[1]), "r"(a[2]), "r"(a[3]), "r"(b0), "r"(b1));
}
__device__ __forceinline__ int clampi(int v, int lo, int hi) {
    return v < lo ? lo : (v > hi ? hi : v);
}
__device__ __forceinline__ void accH(float4& a, const __half2* rowp, int lane) {
    uint2 u = *reinterpret_cast<const uint2*>(rowp + lane * 2);
    __half2 h0 = *reinterpret_cast<__half2*>(&u.x);
    __half2 h1 = *reinterpret_cast<__half2*>(&u.y);
    float2 f0 = __half22float2(h0);
    float2 f1 = __half22float2(h1);
    a.x += f0.x; a.y += f0.y; a.z += f1.x; a.w += f1.y;
}

// ---------------- CSR build ----------------
__global__ void k_count(const int* __restrict__ src, const int* __restrict__ dst, int E) {
    int e4 = (blockIdx.x * blockDim.x + threadIdx.x) * 4;
    if (e4 + 4 <= E) {
        int4 s = *reinterpret_cast<const int4*>(src + e4);
        int4 d = *reinterpret_cast<const int4*>(dst + e4);
        atomicAdd(&g_out_cnt[clampi(s.x, 0, N_NODES - 1)], 1);
        atomicAdd(&g_out_cnt[clampi(s.y, 0, N_NODES - 1)], 1);
        atomicAdd(&g_out_cnt[clampi(s.z, 0, N_NODES - 1)], 1);
        atomicAdd(&g_out_cnt[clampi(s.w, 0, N_NODES - 1)], 1);
        atomicAdd(&g_in_cnt[clampi(d.x, 0, N_NODES - 1)], 1);
        atomicAdd(&g_in_cnt[clampi(d.y, 0, N_NODES - 1)], 1);
        atomicAdd(&g_in_cnt[clampi(d.z, 0, N_NODES - 1)], 1);
        atomicAdd(&g_in_cnt[clampi(d.w, 0, N_NODES - 1)], 1);
    } else {
        for (int e = e4; e < E; e++) {
            atomicAdd(&g_out_cnt[clampi(src[e], 0, N_NODES - 1)], 1);
            atomicAdd(&g_in_cnt[clampi(dst[e], 0, N_NODES - 1)], 1);
        }
    }
}

__global__ void k_scan_a() {
    __shared__ int sh[1024];
    int b = blockIdx.x, t = threadIdx.x, i = b * 1024 + t;
    int v = (i < N_NODES) ? g_in_cnt[i] : 0;
    sh[t] = v;
    __syncthreads();
    for (int off = 1; off < 1024; off <<= 1) {
        int tv = (t >= off) ? sh[t - off] : 0;
        __syncthreads();
        sh[t] += tv;
        __syncthreads();
    }
    if (i < N_NODES) g_row_ofs[i] = sh[t] - v;
    if (t == 1023) g_blk[b] = sh[1023];
}
__global__ void k_scan_b() {
    __shared__ int sh[64];
    int t = threadIdx.x;
    int v = (t < 49) ? g_blk[t] : 0;
    sh[t] = v;
    __syncthreads();
    for (int off = 1; off < 64; off <<= 1) {
        int tv = (t >= off) ? sh[t - off] : 0;
        __syncthreads();
        sh[t] += tv;
        __syncthreads();
    }
    if (t < 49) g_blk[t] = sh[t] - v;
}
__global__ void k_scan_c() {
    int b = blockIdx.x, i = b * 1024 + threadIdx.x;
    if (i < N_NODES && b > 0) g_row_ofs[i] += g_blk[b];
}

// fill uses g_row_ofs itself as cursor; afterwards row_ofs[d] == orig_row_ofs[d+1]
__global__ void k_fill(const int* __restrict__ src, const int* __restrict__ dst, int E) {
    int e4 = (blockIdx.x * blockDim.x + threadIdx.x) * 4;
    if (e4 + 4 <= E) {
        int4 s = *reinterpret_cast<const int4*>(src + e4);
        int4 d = *reinterpret_cast<const int4*>(dst + e4);
        int pos;
        pos = atomicAdd(&g_row_ofs[clampi(d.x, 0, N_NODES - 1)], 1);
        g_csr_src[pos] = clampi(s.x, 0, N_NODES - 1);
        pos = atomicAdd(&g_row_ofs[clampi(d.y, 0, N_NODES - 1)], 1);
        g_csr_src[pos] = clampi(s.y, 0, N_NODES - 1);
        pos = atomicAdd(&g_row_ofs[clampi(d.z, 0, N_NODES - 1)], 1);
        g_csr_src[pos] = clampi(s.z, 0, N_NODES - 1);
        pos = atomicAdd(&g_row_ofs[clampi(d.w, 0, N_NODES - 1)], 1);
        g_csr_src[pos] = clampi(s.w, 0, N_NODES - 1);
    } else {
        for (int e = e4; e < E; e++) {
            int pos = atomicAdd(&g_row_ofs[clampi(dst[e], 0, N_NODES - 1)], 1);
            g_csr_src[pos] = clampi(src[e], 0, N_NODES - 1);
        }
    }
}

// ---------------- prep: Pp = (next_h@W_fus)*tdw ; bias ----------------
__global__ void k_prepP(const float* __restrict__ next_h, const float* __restrict__ W_fus,
                        const float* __restrict__ tdw, const float* __restrict__ b_conv,
                        const float* __restrict__ b_fus, const float* __restrict__ conv_w) {
    __shared__ float sh[16][D];
    int r0 = blockIdx.x * 16;
    int j = threadIdx.x;
    if (blockIdx.x == 0) g_bias[j] = b_conv[j] * conv_w[j] + b_fus[j] * tdw[j];
    #pragma unroll
    for (int r = 0; r < 16; r++) sh[r][j] = next_h[(r0 + r) * D + j];
    __syncthreads();
    float acc[16];
    #pragma unroll
    for (int r = 0; r < 16; r++) acc[r] = 0.f;
    for (int k = 0; k < D; k++) {
        float w = W_fus[k * D + j];
        #pragma unroll
        for (int r = 0; r < 16; r++) acc[r] += sh[r][k] * w;
    }
    float t = tdw[j];
    #pragma unroll
    for (int r = 0; r < 16; r++) g_Pp[(size_t)(r0 + r) * D + j] = acc[r] * t;
}

// pack B into m16n8k16 fp16 fragment order, one 8KB chunk per K-block of 32.
__global__ void k_packB(const float* __restrict__ W_conv, const float* __restrict__ conv_w) {
    int i = blockIdx.x * blockDim.x + threadIdx.x;
    if (i >= NCH_TOT * CHUNK_U32) return;
    int c = i >> 11, rem = i & 2047;
    int e = rem & 1;
    int lane = (rem >> 1) & 31;
    int j = (rem >> 6) & 15;
    int ks = rem >> 10;
    int g = lane >> 2, tg = lane & 3;
    int n = j * 8 + g;
    int kl = ks * 16 + 2 * tg + e * 8;
    float v0, v1;
    if (c < NCH_A) {
        int kg = c * KB + kl;
        v0 = (kg < N_NEXT) ? g_Pp[(size_t)kg * D + n] : 0.f;
        v1 = (kg + 1 < N_NEXT) ? g_Pp[(size_t)(kg + 1) * D + n] : 0.f;
    } else {
        int kg = (c - NCH_A) * KB + kl;
        v0 = W_conv[kg * D + n] * conv_w[n];
        v1 = W_conv[(kg + 1) * D + n] * conv_w[n];
    }
    g_BF[i] = cvt2h(v0, v1);
}

// ---------------- fp16 mma GEMM: H = norm_out .* (inc@Pp + curr_h@Wcp) -> fp16 ----------------
// 256 threads (8 warps), M=128 (16 rows/warp), N=128, K-chunk 32, 3-stage cp.async pipeline.
#define ASTRIDE 40
#define A_TILE_F (128 * ASTRIDE)
#define NSTAGE 3
__global__ __launch_bounds__(256, 2) void k_gemm(const float* __restrict__ curr_h,
                                                 const float* __restrict__ inc) {
    extern __shared__ char smem[];
    float*    sA = reinterpret_cast<float*>(smem);                             // [3][128*40]
    uint32_t* sB = reinterpret_cast<uint32_t*>(smem + NSTAGE * A_TILE_F * 4);  // [3][2048]
    const int tid = threadIdx.x, wid = tid >> 5, lane = tid & 31;
    const int g = lane >> 2, tg = lane & 3;
    const int bm = blockIdx.x * 128;

    float acc[16][4];
    #pragma unroll
    for (int j = 0; j < 16; j++)
        #pragma unroll
        for (int q = 0; q < 4; q++) acc[j][q] = 0.f;

    auto fetch = [&](int c, int buf) {
        const float* Ap; int ld, k0;
        if (c < NCH_A) { Ap = inc; ld = N_NEXT; k0 = c * KB; }
        else           { Ap = curr_h; ld = D; k0 = (c - NCH_A) * KB; }
        #pragma unroll
        for (int q8 = 0; q8 < 4; q8++) {
            int idx = q8 * 256 + tid;
            int row = idx >> 3, quad = idx & 7;
            int grow = bm + row;
            if (grow >= N_NODES) grow = N_NODES - 1;
            int col = k0 + quad * 4;
            float* dstp = sA + buf * A_TILE_F + row * ASTRIDE + quad * 4;
            if (col + 4 <= ld) cp16(smem_u32(dstp), Ap + (size_t)grow * ld + col);
            else *reinterpret_cast<float4*>(dstp) = make_float4(0.f, 0.f, 0.f, 0.f);
        }
        const uint32_t* srcb = g_BF + (size_t)c * CHUNK_U32 + tid * 8;
        uint32_t dstb = smem_u32(sB + buf * CHUNK_U32 + tid * 8);
        cp16(dstb, srcb); cp16(dstb + 16, srcb + 4);
        asm volatile("cp.async.commit_group;" ::: "memory");
    };

    auto compute = [&](int buf) {
        const float* sa = sA + buf * A_TILE_F;
        const uint32_t* sb = sB + buf * CHUNK_U32;
        #pragma unroll
        for (int ks = 0; ks < 2; ks++) {
            const float* base = sa + wid * 16 * ASTRIDE + ks * 16 + 2 * tg;
            float2 p0 = *reinterpret_cast<const float2*>(base + g * ASTRIDE);
            float2 p1 = *reinterpret_cast<const float2*>(base + (g + 8) * ASTRIDE);
            float2 p2 = *reinterpret_cast<const float2*>(base + g * ASTRIDE + 8);
            float2 p3 = *reinterpret_cast<const float2*>(base + (g + 8) * ASTRIDE + 8);
            uint32_t af[4];
            af[0] = cvt2h(p0.x, p0.y);
            af[1] = cvt2h(p1.x, p1.y);
            af[2] = cvt2h(p2.x, p2.y);
            af[3] = cvt2h(p3.x, p3.y);
            #pragma unroll
            for (int j = 0; j < 16; j++) {
                uint2 b = *reinterpret_cast<const uint2*>(sb + (ks * 16 + j) * 64 + lane * 2);
                mma16(acc[j], af, b.x, b.y);
            }
        }
    };

    fetch(0, 0);
    fetch(1, 1);
    int buf = 0;
    for (int c = 0; c < NCH_TOT; ++c) {
        if (c + 2 < NCH_TOT) {
            int nb = buf + 2; if (nb >= NSTAGE) nb -= NSTAGE;
            fetch(c + 2, nb);
            asm volatile("cp.async.wait_group 2;" ::: "memory");
        } else if (c + 1 < NCH_TOT) {
            asm volatile("cp.async.wait_group 1;" ::: "memory");
        } else {
            asm volatile("cp.async.wait_group 0;" ::: "memory");
        }
        __syncthreads();
        compute(buf);
        __syncthreads();
        if (++buf == NSTAGE) buf = 0;
    }

    // epilogue: apply norm_out, convert to fp16, write H
    int r0 = bm + wid * 16 + g;
    int r1 = r0 + 8;
    if (r0 < N_NODES) {
        float no = rsqrtf((float)(g_out_cnt[r0] + 1));
        __half2* dp = g_Hh + (size_t)r0 * 64 + tg;
        #pragma unroll
        for (int j = 0; j < 16; j++)
            dp[j * 4] = __floats2half2_rn(acc[j][0] * no, acc[j][1] * no);
    }
    if (r1 < N_NODES) {
        float no = rsqrtf((float)(g_out_cnt[r1] + 1));
        __half2* dp = g_Hh + (size_t)r1 * 64 + tg;
        #pragma unroll
        for (int j = 0; j < 16; j++)
            dp[j * 4] = __floats2half2_rn(acc[j][2] * no, acc[j][3] * no);
    }
}
#define GEMM_SMEM (NSTAGE * (A_TILE_F * 4 + CHUNK_U32 * 4))

// ---------------- gather + norm_in + bias + LayerNorm + ReLU ----------------
// note: g_row_ofs was mutated by k_fill: row_ofs[d] == original row_ofs[d+1]
__global__ void k_gather(const float* __restrict__ ln_g, const float* __restrict__ ln_b,
                         float* __restrict__ out) {
    int warp = (blockIdx.x * blockDim.x + threadIdx.x) >> 5;
    int lane = threadIdx.x & 31;
    if (warp >= N_NODES) return;

    float4 a0 = make_float4(0.f, 0.f, 0.f, 0.f), a1 = a0, a2 = a0, a3 = a0;
    accH(a0, g_Hh + (size_t)warp * 64, lane);       // self-loop
    int beg = (warp == 0) ? 0 : __ldg(g_row_ofs + warp - 1);
    int end = __ldg(g_row_ofs + warp);

    int j = beg;
    for (; j + 4 <= end; j += 4) {
        int s0 = __ldg(g_csr_src + j);
        int s1 = __ldg(g_csr_src + j + 1);
        int s2 = __ldg(g_csr_src + j + 2);
        int s3 = __ldg(g_csr_src + j + 3);
        accH(a0, g_Hh + (size_t)s0 * 64, lane);
        accH(a1, g_Hh + (size_t)s1 * 64, lane);
        accH(a2, g_Hh + (size_t)s2 * 64, lane);
        accH(a3, g_Hh + (size_t)s3 * 64, lane);
    }
    for (; j < end; j++) {
        int s = __ldg(g_csr_src + j);
        accH(a0, g_Hh + (size_t)s * 64, lane);
    }
    float4 acc;
    acc.x = (a0.x + a1.x) + (a2.x + a3.x);
    acc.y = (a0.y + a1.y) + (a2.y + a3.y);
    acc.z = (a0.z + a1.z) + (a2.z + a3.z);
    acc.w = (a0.w + a1.w) + (a2.w + a3.w);

    float ni = rsqrtf((float)(end - beg + 1));
    int c0 = lane * 4;
    float x0 = acc.x * ni + g_bias[c0 + 0];
    float x1 = acc.y * ni + g_bias[c0 + 1];
    float x2 = acc.z * ni + g_bias[c0 + 2];
    float x3 = acc.w * ni + g_bias[c0 + 3];

    float s = x0 + x1 + x2 + x3;
    #pragma unroll
    for (int off = 16; off > 0; off >>= 1) s += __shfl_xor_sync(0xffffffffu, s, off);
    float mu = s * (1.0f / D);
    float d0 = x0 - mu, d1 = x1 - mu, d2 = x2 - mu, d3 = x3 - mu;
    float q = d0 * d0 + d1 * d1 + d2 * d2 + d3 * d3;
    #pragma unroll
    for (int off = 16; off > 0; off >>= 1) q += __shfl_xor_sync(0xffffffffu, q, off);
    float inv = rsqrtf(q * (1.0f / D) + 1e-5f);

    float4 o;
    o.x = fmaxf(d0 * inv * ln_g[c0 + 0] + ln_b[c0 + 0], 0.f);
    o.y = fmaxf(d1 * inv * ln_g[c0 + 1] + ln_b[c0 + 1], 0.f);
    o.z = fmaxf(d2 * inv * ln_g[c0 + 2] + ln_b[c0 + 2], 0.f);
    o.w = fmaxf(d3 * inv * ln_g[c0 + 3] + ln_b[c0 + 3], 0.f);
    reinterpret_cast<float4*>(out + (size_t)warp * D)[lane] = o;
}

// ---------------- launcher (forked-stream graph) ----------------
extern "C" void kernel_launch(void* const* d_in, const int* in_sizes, int n_in,
                              void* d_out, int out_size) {
    const float* curr_h = (const float*)d_in[0];
    const float* next_h = (const float*)d_in[1];
    const float* inc    = (const float*)d_in[2];
    const int*   src    = (const int*)d_in[3];
    const int*   dst    = (const int*)d_in[4];
    const float* W_conv = (const float*)d_in[5];
    const float* b_conv = (const float*)d_in[6];
    const float* W_fus  = (const float*)d_in[7];
    const float* b_fus  = (const float*)d_in[8];
    const float* conv_w = (const float*)d_in[9];
    const float* tdw    = (const float*)d_in[10];
    const float* ln_g   = (const float*)d_in[11];
    const float* ln_b   = (const float*)d_in[12];
    float* out = (float*)d_out;
    const int E = in_sizes[3];

    static cudaStream_t s1 = nullptr, s2 = nullptr;
    static cudaEvent_t evRoot, evCount, evCsr, evGemm;
    static void *p_in, *p_out;
    if (!s1) {
        cudaStreamCreateWithFlags(&s1, cudaStreamNonBlocking);
        cudaStreamCreateWithFlags(&s2, cudaStreamNonBlocking);
        cudaEventCreateWithFlags(&evRoot, cudaEventDisableTiming);
        cudaEventCreateWithFlags(&evCount, cudaEventDisableTiming);
        cudaEventCreateWithFlags(&evCsr, cudaEventDisableTiming);
        cudaEventCreateWithFlags(&evGemm, cudaEventDisableTiming);
        cudaFuncSetAttribute(k_gemm, cudaFuncAttributeMaxDynamicSharedMemorySize, GEMM_SMEM);
        cudaGetSymbolAddress(&p_in, g_in_cnt);
        cudaGetSymbolAddress(&p_out, g_out_cnt);
    }

    // fork both worker streams off the (captured) default stream
    cudaEventRecord(evRoot, 0);
    cudaStreamWaitEvent(s1, evRoot, 0);
    cudaStreamWaitEvent(s2, evRoot, 0);

    // --- chain 1: CSR build ---
    cudaMemsetAsync(p_in, 0, N_NODES * sizeof(int), s1);
    cudaMemsetAsync(p_out, 0, N_NODES * sizeof(int), s1);
    k_count<<<(E / 4 + 255) / 256, 256, 0, s1>>>(src, dst, E);
    cudaEventRecord(evCount, s1);
    k_scan_a<<<49, 1024, 0, s1>>>();
    k_scan_b<<<1, 64, 0, s1>>>();
    k_scan_c<<<49, 1024, 0, s1>>>();
    k_fill<<<(E / 4 + 255) / 256, 256, 0, s1>>>(src, dst, E);
    cudaEventRecord(evCsr, s1);

    // --- chain 2: dense path ---
    k_prepP<<<N_NEXT / 16, 128, 0, s2>>>(next_h, W_fus, tdw, b_conv, b_fus, conv_w);
    k_packB<<<(NCH_TOT * CHUNK_U32 + 255) / 256, 256, 0, s2>>>(W_conv, conv_w);
    cudaStreamWaitEvent(s2, evCount, 0);     // gemm epilogue reads g_out_cnt
    k_gemm<<<(N_NODES + 127) / 128, 256, GEMM_SMEM, s2>>>(curr_h, inc);
    cudaEventRecord(evGemm, s2);

    // --- join on default stream, then gather ---
    cudaStreamWaitEvent(0, evCsr, 0);
    cudaStreamWaitEvent(0, evGemm, 0);
    k_gather<<<(N_NODES * 32 + 255) / 256, 256>>>(ln_g, ln_b, out);
}